// round 15
// baseline (speedup 1.0000x reference)
#include <cuda_runtime.h>
#include <cuda_bf16.h>
#include <cstdint>

#define DIN 512
#define DOUT 64
#define NEG_SLOPE 0.2f
#define N_MAX 100000
#define E_MAX 1600000

// ---------------- scratch (__device__ globals; no allocation allowed) ------
__device__ float    g_support[(size_t)N_MAX * DOUT];
__device__ unsigned g_Wp[32768];       // W as bf16 hi/lo, fragment-permuted

__device__ int    g_rowptr[N_MAX + 1];
__device__ int    g_tmpoff[N_MAX];
__device__ int    g_bsums[128];
__device__ float2 g_ecf[E_MAX];        // packed {col_bits, val}, row-sorted

// ---------------------------------------------------------------------------
// helpers
// ---------------------------------------------------------------------------
__device__ __forceinline__ unsigned pk(float lo, float hi) {
    unsigned r;
    asm("cvt.rn.bf16x2.f32 %0, %1, %2;" : "=r"(r) : "f"(hi), "f"(lo));
    return r;
}

__device__ __forceinline__ void mma_bf16(float c[4],
                                         unsigned a0, unsigned a1, unsigned a2, unsigned a3,
                                         unsigned b0, unsigned b1)
{
    asm volatile(
        "mma.sync.aligned.m16n8k16.row.col.f32.bf16.bf16.f32 "
        "{%0,%1,%2,%3}, {%4,%5,%6,%7}, {%8,%9}, {%0,%1,%2,%3};"
        : "+f"(c[0]), "+f"(c[1]), "+f"(c[2]), "+f"(c[3])
        : "r"(a0), "r"(a1), "r"(a2), "r"(a3), "r"(b0), "r"(b1));
}

// ---------------------------------------------------------------------------
// W pack: bf16 hi + bf16 residual lo, permuted to mma-fragment order (R6-proven)
// ---------------------------------------------------------------------------
__global__ void pack_w_kernel(const float* __restrict__ W, unsigned* __restrict__ Wp)
{
    int i = blockIdx.x * blockDim.x + threadIdx.x;
    if (i >= (DIN / 2) * DOUT) return;
    int k2 = i >> 6, nn = i & 63;
    float w0 = W[(2 * k2) * DOUT + nn];
    float w1 = W[(2 * k2 + 1) * DOUT + nn];
    unsigned hv = pk(w0, w1);
    float r0 = w0 - __uint_as_float(hv << 16);
    float r1 = w1 - __uint_as_float(hv & 0xffff0000u);
    unsigned lv = pk(r0, r1);

    int kc = k2 >> 4, k2l = k2 & 15;
    int kk = k2l >> 3, t_ = k2l & 7, tt = t_ & 3, bs = t_ >> 2;
    int j = nn >> 3, gg = nn & 7, lane = gg * 4 + tt;
    int c = bs * 2 + (j >> 2), e = j & 3;
    int lin = (((kc * 2 + kk) * 8 + c) * 32 + lane) * 4 + e;
    Wp[lin] = hv;
    Wp[lin + 512] = lv;           // lo chunks sit 4 chunks (512 u32) later
}

// ---------------------------------------------------------------------------
// GEMM: C = leaky_relu(A @ W) via 3x bf16-split mma.sync.m16n8k16 (R6-proven)
// BM=128, BK=32, 256 thr / 8 warps; double-buffered dynamic smem.
// ---------------------------------------------------------------------------
#define BM 128
#define GEMM_SMEM_BYTES (2 * 7168 * 4)

__global__ __launch_bounds__(256) void gemm_bf16x3_kernel(
    const float* __restrict__ A, const unsigned* __restrict__ Wp,
    float* __restrict__ C, int n)
{
    extern __shared__ unsigned sm[];
    const int tid  = threadIdx.x;
    const int warp = tid >> 5;
    const int lane = tid & 31;
    const int g = lane >> 2;
    const int t = lane & 3;
    const int row0 = blockIdx.x * BM;
    const int am = tid >> 3;          // 0..31
    const int ak = (tid & 7) << 2;    // 0..28
    const int p0 = ak >> 1;

    float acc[8][4];
    #pragma unroll
    for (int j = 0; j < 8; j++)
        #pragma unroll
        for (int q = 0; q < 4; q++) acc[j][q] = 0.f;

    float4 aR[4];
    uint4  bR[2];

    auto ldg = [&](int chunk) {
        const int k0 = chunk * 32;
        #pragma unroll
        for (int p = 0; p < 4; p++) {
            int r = row0 + am + p * 32;
            aR[p] = (r < n) ? *reinterpret_cast<const float4*>(A + (size_t)r * DIN + k0 + ak)
                            : make_float4(0.f, 0.f, 0.f, 0.f);
        }
        const uint4* gb = reinterpret_cast<const uint4*>(Wp + chunk * 2048 + tid * 8);
        bR[0] = gb[0];
        bR[1] = gb[1];
    };

    auto sts = [&](int buf) {
        unsigned* Ah = sm + buf * 7168;
        unsigned* Al = Ah + 2560;
        unsigned* Bb = Ah + 5120;
        #pragma unroll
        for (int p = 0; p < 4; p++) {
            int rl = am + p * 32;
            float4 v = aR[p];
            unsigned h01 = pk(v.x, v.y), h23 = pk(v.z, v.w);
            float r0 = v.x - __uint_as_float(h01 << 16);
            float r1 = v.y - __uint_as_float(h01 & 0xffff0000u);
            float r2 = v.z - __uint_as_float(h23 << 16);
            float r3 = v.w - __uint_as_float(h23 & 0xffff0000u);
            unsigned l01 = pk(r0, r1), l23 = pk(r2, r3);
            Ah[rl * 20 + p0]     = h01;
            Ah[rl * 20 + p0 + 1] = h23;
            Al[rl * 20 + p0]     = l01;
            Al[rl * 20 + p0 + 1] = l23;
        }
        uint4* sb = reinterpret_cast<uint4*>(Bb + tid * 8);
        sb[0] = bR[0];
        sb[1] = bR[1];
    };

    auto compute = [&](int buf) {
        const unsigned* Ah = sm + buf * 7168;
        const unsigned* Al = Ah + 2560;
        const unsigned* Bb = Ah + 5120;
        #pragma unroll
        for (int kk = 0; kk < 2; kk++) {
            const int rb = (warp * 16 + g) * 20 + kk * 8 + t;
            const unsigned ah0 = Ah[rb],       ah1 = Ah[rb + 160];
            const unsigned ah2 = Ah[rb + 4],   ah3 = Ah[rb + 164];
            const unsigned al0 = Al[rb],       al1 = Al[rb + 160];
            const unsigned al2 = Al[rb + 4],   al3 = Al[rb + 164];
            uint4 q[8];
            #pragma unroll
            for (int c = 0; c < 8; c++)
                q[c] = *reinterpret_cast<const uint4*>(Bb + kk * 1024 + (c * 32 + lane) * 4);
            #pragma unroll
            for (int j = 0; j < 8; j++) {
                const uint4 h0 = q[(j >> 2)];
                const uint4 h1 = q[2 + (j >> 2)];
                const uint4 l0 = q[4 + (j >> 2)];
                const uint4 l1 = q[6 + (j >> 2)];
                const int e = j & 3;
                const unsigned b0h = (e == 0) ? h0.x : (e == 1) ? h0.y : (e == 2) ? h0.z : h0.w;
                const unsigned b1h = (e == 0) ? h1.x : (e == 1) ? h1.y : (e == 2) ? h1.z : h1.w;
                const unsigned b0l = (e == 0) ? l0.x : (e == 1) ? l0.y : (e == 2) ? l0.z : l0.w;
                const unsigned b1l = (e == 0) ? l1.x : (e == 1) ? l1.y : (e == 2) ? l1.z : l1.w;
                mma_bf16(acc[j], ah0, ah1, ah2, ah3, b0h, b1h);   // Ah*Bh
                mma_bf16(acc[j], al0, al1, al2, al3, b0h, b1h);   // Al*Bh
                mma_bf16(acc[j], ah0, ah1, ah2, ah3, b0l, b1l);   // Ah*Bl
            }
        }
    };

    ldg(0);
    sts(0);
    __syncthreads();
    #pragma unroll 1
    for (int i = 0; i < 16; i++) {
        const int cur = i & 1;
        if (i + 1 < 16) ldg(i + 1);
        compute(cur);
        if (i + 1 < 16) sts(1 - cur);
        __syncthreads();
    }

    // epilogue: LeakyReLU + float2 stores
    const int rA = row0 + warp * 16 + g;
    const int rB = rA + 8;
    const bool okA = rA < n, okB = rB < n;
    #pragma unroll
    for (int j = 0; j < 8; j++) {
        const int col = j * 8 + 2 * t;
        if (okA) {
            float2 v;
            v.x = acc[j][0]; v.x = (v.x > 0.f) ? v.x : NEG_SLOPE * v.x;
            v.y = acc[j][1]; v.y = (v.y > 0.f) ? v.y : NEG_SLOPE * v.y;
            *reinterpret_cast<float2*>(C + (size_t)rA * DOUT + col) = v;
        }
        if (okB) {
            float2 v;
            v.x = acc[j][2]; v.x = (v.x > 0.f) ? v.x : NEG_SLOPE * v.x;
            v.y = acc[j][3]; v.y = (v.y > 0.f) ? v.y : NEG_SLOPE * v.y;
            *reinterpret_cast<float2*>(C + (size_t)rB * DOUT + col) = v;
        }
    }
}

// ---------------------------------------------------------------------------
// CSR build: scalar histogram -> 2-level scan -> fused offsets+copy -> scatter
// ---------------------------------------------------------------------------
__global__ void hist_kernel(const int* __restrict__ rows, int* __restrict__ cnt, int E)
{
    int i = blockIdx.x * blockDim.x + threadIdx.x;
    if (i < E) atomicAdd(cnt + rows[i], 1);
}

#define SCAN_B 1024
__global__ __launch_bounds__(SCAN_B) void scan_blocks_kernel(
    const int* __restrict__ cnt, int* __restrict__ rowptr,
    int* __restrict__ bsums, int n)
{
    __shared__ int s[SCAN_B];
    const int tid = threadIdx.x;
    const int i = blockIdx.x * SCAN_B + tid;
    int v = (i < n) ? cnt[i] : 0;
    s[tid] = v;
    __syncthreads();
    #pragma unroll
    for (int off = 1; off < SCAN_B; off <<= 1) {
        int t = (tid >= off) ? s[tid - off] : 0;
        __syncthreads();
        s[tid] += t;
        __syncthreads();
    }
    if (i < n) rowptr[i] = s[tid] - v;
    if (tid == SCAN_B - 1) bsums[blockIdx.x] = s[tid];
}

__global__ __launch_bounds__(128) void scan_sums_kernel(int* __restrict__ bsums, int nb)
{
    __shared__ int s[128];
    const int tid = threadIdx.x;
    int v = (tid < nb) ? bsums[tid] : 0;
    s[tid] = v;
    __syncthreads();
    #pragma unroll
    for (int off = 1; off < 128; off <<= 1) {
        int t = (tid >= off) ? s[tid - off] : 0;
        __syncthreads();
        s[tid] += t;
        __syncthreads();
    }
    if (tid < nb) bsums[tid] = s[tid] - v;
}

// fused: finalize rowptr AND write the scatter-offset working copy
__global__ void add_offsets_copy_kernel(int* __restrict__ rowptr,
                                        int* __restrict__ tmpoff,
                                        const int* __restrict__ bsums, int n, int E)
{
    int i = blockIdx.x * blockDim.x + threadIdx.x;
    if (i < n) {
        int v = rowptr[i] + bsums[i >> 10];
        rowptr[i] = v;
        tmpoff[i] = v;
    }
    if (i == 0) rowptr[n] = E;
}

__global__ void scatter_kernel(const int* __restrict__ rows,
                               const int* __restrict__ cols,
                               const float* __restrict__ vals,
                               int* __restrict__ off,
                               float2* __restrict__ ecf, int E)
{
    int i = blockIdx.x * blockDim.x + threadIdx.x;
    if (i < E) {
        int r = rows[i];
        int p = atomicAdd(off + r, 1);
        ecf[p] = make_float2(__int_as_float(cols[i]), vals[i]);
    }
}

// ---------------------------------------------------------------------------
// CSR SpMM (R6-proven, unroll 2): 16 threads/row, float4/thread, no atomics.
// ---------------------------------------------------------------------------
__global__ __launch_bounds__(256) void spmm_csr_kernel(
    const int* __restrict__ rowptr, const float2* __restrict__ ecf,
    const float* __restrict__ x, float* __restrict__ out, int n)
{
    const int tid = threadIdx.x;
    const int row = blockIdx.x * 16 + (tid >> 4);
    const int c4 = (tid & 15) << 2;
    if (row >= n) return;

    const int s = __ldg(rowptr + row);
    const int e = __ldg(rowptr + row + 1);

    float4 a0 = make_float4(0.f, 0.f, 0.f, 0.f);
    float4 a1 = make_float4(0.f, 0.f, 0.f, 0.f);

    int i = s;
    for (; i + 2 <= e; i += 2) {
        const float2 cv0 = __ldg(ecf + i);
        const float2 cv1 = __ldg(ecf + i + 1);
        const int c0 = __float_as_int(cv0.x);
        const int c1 = __float_as_int(cv1.x);
        const float4 x0 = __ldg(reinterpret_cast<const float4*>(x + ((size_t)c0 << 6) + c4));
        const float4 x1 = __ldg(reinterpret_cast<const float4*>(x + ((size_t)c1 << 6) + c4));
        a0.x = fmaf(cv0.y, x0.x, a0.x); a0.y = fmaf(cv0.y, x0.y, a0.y);
        a0.z = fmaf(cv0.y, x0.z, a0.z); a0.w = fmaf(cv0.y, x0.w, a0.w);
        a1.x = fmaf(cv1.y, x1.x, a1.x); a1.y = fmaf(cv1.y, x1.y, a1.y);
        a1.z = fmaf(cv1.y, x1.z, a1.z); a1.w = fmaf(cv1.y, x1.w, a1.w);
    }
    if (i < e) {
        const float2 cv = __ldg(ecf + i);
        const int c0 = __float_as_int(cv.x);
        const float4 x0 = __ldg(reinterpret_cast<const float4*>(x + ((size_t)c0 << 6) + c4));
        a0.x = fmaf(cv.y, x0.x, a0.x); a0.y = fmaf(cv.y, x0.y, a0.y);
        a0.z = fmaf(cv.y, x0.z, a0.z); a0.w = fmaf(cv.y, x0.w, a0.w);
    }

    float4 r;
    r.x = a0.x + a1.x; r.y = a0.y + a1.y; r.z = a0.z + a1.z; r.w = a0.w + a1.w;
    *reinterpret_cast<float4*>(out + ((size_t)row << 6) + c4) = r;
}

// ---------------------------------------------------------------------------
// kernel_launch: fork the (GEMM-independent) CSR build onto a side stream so
// the captured graph overlaps it with the GEMM; join before SpMM-1.
// Stream/event handles are intentionally NOT destroyed (destroy during an
// active capture invalidates it; kernel_launch runs only a handful of times,
// and streams/events are not device-memory allocations).
// ---------------------------------------------------------------------------
extern "C" void kernel_launch(void* const* d_in, const int* in_sizes, int n_in,
                              void* d_out, int out_size)
{
    const float* features = (const float*)d_in[0];
    const float* weight   = (const float*)d_in[1];
    const int*   erows    = (const int*)d_in[2];
    const int*   ecols    = (const int*)d_in[3];
    const float* evals    = (const float*)d_in[4];
    float* out = (float*)d_out;

    const int n = in_sizes[0] / DIN;
    const int E = in_sizes[2];

    float* out_output = out;
    float* out_az     = out + (size_t)n * DOUT;

    float*    support = nullptr;
    unsigned* wp = nullptr;
    int *rowptr = nullptr, *tmpoff = nullptr, *bsums = nullptr;
    float2* ecf = nullptr;
    cudaGetSymbolAddress((void**)&support, g_support);
    cudaGetSymbolAddress((void**)&wp, g_Wp);
    cudaGetSymbolAddress((void**)&rowptr, g_rowptr);
    cudaGetSymbolAddress((void**)&tmpoff, g_tmpoff);
    cudaGetSymbolAddress((void**)&bsums, g_bsums);
    cudaGetSymbolAddress((void**)&ecf, g_ecf);

    cudaStream_t s2;
    cudaEvent_t  eFork, eJoin;
    cudaStreamCreateWithFlags(&s2, cudaStreamNonBlocking);
    cudaEventCreateWithFlags(&eFork, cudaEventDisableTiming);
    cudaEventCreateWithFlags(&eJoin, cudaEventDisableTiming);

    // ---- fork: side stream joins the capture graph ----
    cudaEventRecord(eFork, 0);
    cudaStreamWaitEvent(s2, eFork, 0);

    // ---- chain B (side stream): CSR build, independent of GEMM ----
    cudaMemsetAsync(tmpoff, 0, (size_t)n * sizeof(int), s2);
    hist_kernel<<<(E + 255) / 256, 256, 0, s2>>>(erows, tmpoff, E);
    const int nblocks = (n + SCAN_B - 1) / SCAN_B;
    scan_blocks_kernel<<<nblocks, SCAN_B, 0, s2>>>(tmpoff, rowptr, bsums, n);
    scan_sums_kernel<<<1, 128, 0, s2>>>(bsums, nblocks);
    add_offsets_copy_kernel<<<(n + 255) / 256, 256, 0, s2>>>(rowptr, tmpoff, bsums, n, E);
    scatter_kernel<<<(E + 255) / 256, 256, 0, s2>>>(erows, ecols, evals, tmpoff, ecf, E);
    cudaEventRecord(eJoin, s2);

    // ---- chain A (main stream): W pack + GEMM ----
    pack_w_kernel<<<((DIN / 2) * DOUT + 255) / 256, 256>>>(weight, wp);
    cudaFuncSetAttribute(gemm_bf16x3_kernel,
                         cudaFuncAttributeMaxDynamicSharedMemorySize, GEMM_SMEM_BYTES);
    gemm_bf16x3_kernel<<<(n + BM - 1) / BM, 256, GEMM_SMEM_BYTES>>>(features, wp, support, n);

    // ---- join: SpMMs need both support and the CSR ----
    cudaStreamWaitEvent(0, eJoin, 0);

    // ---- Phase 2: output = adj @ support ----
    spmm_csr_kernel<<<(n + 15) / 16, 256>>>(rowptr, ecf, support, out_output, n);

    // ---- Phase 3: az = adj @ output ----
    spmm_csr_kernel<<<(n + 15) / 16, 256>>>(rowptr, ecf, out_output, out_az, n);
}

// round 16
// speedup vs baseline: 1.0029x; 1.0029x over previous
#include <cuda_runtime.h>
#include <cuda_bf16.h>
#include <cstdint>

#define DIN 512
#define DOUT 64
#define NEG_SLOPE 0.2f
#define N_MAX 100000
#define E_MAX 1600000

// ---------------- scratch (__device__ globals; no allocation allowed) ------
__device__ float    g_support[(size_t)N_MAX * DOUT];
__device__ unsigned g_Wp[32768];       // W as bf16 hi/lo, fragment-permuted

__device__ int    g_rowptr[N_MAX + 1];
__device__ int    g_tmpoff[N_MAX];
__device__ int    g_bsums[128];
__device__ float2 g_ecf[E_MAX];        // packed {col_bits, val}, row-sorted

// ---------------------------------------------------------------------------
// helpers
// ---------------------------------------------------------------------------
__device__ __forceinline__ unsigned pk(float lo, float hi) {
    unsigned r;
    asm("cvt.rn.bf16x2.f32 %0, %1, %2;" : "=r"(r) : "f"(hi), "f"(lo));
    return r;
}

__device__ __forceinline__ void mma_bf16(float c[4],
                                         unsigned a0, unsigned a1, unsigned a2, unsigned a3,
                                         unsigned b0, unsigned b1)
{
    asm volatile(
        "mma.sync.aligned.m16n8k16.row.col.f32.bf16.bf16.f32 "
        "{%0,%1,%2,%3}, {%4,%5,%6,%7}, {%8,%9}, {%0,%1,%2,%3};"
        : "+f"(c[0]), "+f"(c[1]), "+f"(c[2]), "+f"(c[3])
        : "r"(a0), "r"(a1), "r"(a2), "r"(a3), "r"(b0), "r"(b1));
}

// ---------------------------------------------------------------------------
// W pack: bf16 hi + bf16 residual lo, permuted to mma-fragment order (R6-proven)
// ---------------------------------------------------------------------------
__global__ void pack_w_kernel(const float* __restrict__ W, unsigned* __restrict__ Wp)
{
    int i = blockIdx.x * blockDim.x + threadIdx.x;
    if (i >= (DIN / 2) * DOUT) return;
    int k2 = i >> 6, nn = i & 63;
    float w0 = W[(2 * k2) * DOUT + nn];
    float w1 = W[(2 * k2 + 1) * DOUT + nn];
    unsigned hv = pk(w0, w1);
    float r0 = w0 - __uint_as_float(hv << 16);
    float r1 = w1 - __uint_as_float(hv & 0xffff0000u);
    unsigned lv = pk(r0, r1);

    int kc = k2 >> 4, k2l = k2 & 15;
    int kk = k2l >> 3, t_ = k2l & 7, tt = t_ & 3, bs = t_ >> 2;
    int j = nn >> 3, gg = nn & 7, lane = gg * 4 + tt;
    int c = bs * 2 + (j >> 2), e = j & 3;
    int lin = (((kc * 2 + kk) * 8 + c) * 32 + lane) * 4 + e;
    Wp[lin] = hv;
    Wp[lin + 512] = lv;           // lo chunks sit 4 chunks (512 u32) later
}

// ---------------------------------------------------------------------------
// GEMM: C = leaky_relu(A @ W) via 3x bf16-split mma.sync.m16n8k16 (R6-proven)
// BM=128, BK=32, 256 thr / 8 warps; double-buffered dynamic smem.
// ---------------------------------------------------------------------------
#define BM 128
#define GEMM_SMEM_BYTES (2 * 7168 * 4)

__global__ __launch_bounds__(256) void gemm_bf16x3_kernel(
    const float* __restrict__ A, const unsigned* __restrict__ Wp,
    float* __restrict__ C, int n)
{
    extern __shared__ unsigned sm[];
    const int tid  = threadIdx.x;
    const int warp = tid >> 5;
    const int lane = tid & 31;
    const int g = lane >> 2;
    const int t = lane & 3;
    const int row0 = blockIdx.x * BM;
    const int am = tid >> 3;          // 0..31
    const int ak = (tid & 7) << 2;    // 0..28
    const int p0 = ak >> 1;

    float acc[8][4];
    #pragma unroll
    for (int j = 0; j < 8; j++)
        #pragma unroll
        for (int q = 0; q < 4; q++) acc[j][q] = 0.f;

    float4 aR[4];
    uint4  bR[2];

    auto ldg = [&](int chunk) {
        const int k0 = chunk * 32;
        #pragma unroll
        for (int p = 0; p < 4; p++) {
            int r = row0 + am + p * 32;
            aR[p] = (r < n) ? *reinterpret_cast<const float4*>(A + (size_t)r * DIN + k0 + ak)
                            : make_float4(0.f, 0.f, 0.f, 0.f);
        }
        const uint4* gb = reinterpret_cast<const uint4*>(Wp + chunk * 2048 + tid * 8);
        bR[0] = gb[0];
        bR[1] = gb[1];
    };

    auto sts = [&](int buf) {
        unsigned* Ah = sm + buf * 7168;
        unsigned* Al = Ah + 2560;
        unsigned* Bb = Ah + 5120;
        #pragma unroll
        for (int p = 0; p < 4; p++) {
            int rl = am + p * 32;
            float4 v = aR[p];
            unsigned h01 = pk(v.x, v.y), h23 = pk(v.z, v.w);
            float r0 = v.x - __uint_as_float(h01 << 16);
            float r1 = v.y - __uint_as_float(h01 & 0xffff0000u);
            float r2 = v.z - __uint_as_float(h23 << 16);
            float r3 = v.w - __uint_as_float(h23 & 0xffff0000u);
            unsigned l01 = pk(r0, r1), l23 = pk(r2, r3);
            Ah[rl * 20 + p0]     = h01;
            Ah[rl * 20 + p0 + 1] = h23;
            Al[rl * 20 + p0]     = l01;
            Al[rl * 20 + p0 + 1] = l23;
        }
        uint4* sb = reinterpret_cast<uint4*>(Bb + tid * 8);
        sb[0] = bR[0];
        sb[1] = bR[1];
    };

    auto compute = [&](int buf) {
        const unsigned* Ah = sm + buf * 7168;
        const unsigned* Al = Ah + 2560;
        const unsigned* Bb = Ah + 5120;
        #pragma unroll
        for (int kk = 0; kk < 2; kk++) {
            const int rb = (warp * 16 + g) * 20 + kk * 8 + t;
            const unsigned ah0 = Ah[rb],       ah1 = Ah[rb + 160];
            const unsigned ah2 = Ah[rb + 4],   ah3 = Ah[rb + 164];
            const unsigned al0 = Al[rb],       al1 = Al[rb + 160];
            const unsigned al2 = Al[rb + 4],   al3 = Al[rb + 164];
            uint4 q[8];
            #pragma unroll
            for (int c = 0; c < 8; c++)
                q[c] = *reinterpret_cast<const uint4*>(Bb + kk * 1024 + (c * 32 + lane) * 4);
            #pragma unroll
            for (int j = 0; j < 8; j++) {
                const uint4 h0 = q[(j >> 2)];
                const uint4 h1 = q[2 + (j >> 2)];
                const uint4 l0 = q[4 + (j >> 2)];
                const uint4 l1 = q[6 + (j >> 2)];
                const int e = j & 3;
                const unsigned b0h = (e == 0) ? h0.x : (e == 1) ? h0.y : (e == 2) ? h0.z : h0.w;
                const unsigned b1h = (e == 0) ? h1.x : (e == 1) ? h1.y : (e == 2) ? h1.z : h1.w;
                const unsigned b0l = (e == 0) ? l0.x : (e == 1) ? l0.y : (e == 2) ? l0.z : l0.w;
                const unsigned b1l = (e == 0) ? l1.x : (e == 1) ? l1.y : (e == 2) ? l1.z : l1.w;
                mma_bf16(acc[j], ah0, ah1, ah2, ah3, b0h, b1h);   // Ah*Bh
                mma_bf16(acc[j], al0, al1, al2, al3, b0h, b1h);   // Al*Bh
                mma_bf16(acc[j], ah0, ah1, ah2, ah3, b0l, b1l);   // Ah*Bl
            }
        }
    };

    ldg(0);
    sts(0);
    __syncthreads();
    #pragma unroll 1
    for (int i = 0; i < 16; i++) {
        const int cur = i & 1;
        if (i + 1 < 16) ldg(i + 1);
        compute(cur);
        if (i + 1 < 16) sts(1 - cur);
        __syncthreads();
    }

    // epilogue: LeakyReLU + float2 stores
    const int rA = row0 + warp * 16 + g;
    const int rB = rA + 8;
    const bool okA = rA < n, okB = rB < n;
    #pragma unroll
    for (int j = 0; j < 8; j++) {
        const int col = j * 8 + 2 * t;
        if (okA) {
            float2 v;
            v.x = acc[j][0]; v.x = (v.x > 0.f) ? v.x : NEG_SLOPE * v.x;
            v.y = acc[j][1]; v.y = (v.y > 0.f) ? v.y : NEG_SLOPE * v.y;
            *reinterpret_cast<float2*>(C + (size_t)rA * DOUT + col) = v;
        }
        if (okB) {
            float2 v;
            v.x = acc[j][2]; v.x = (v.x > 0.f) ? v.x : NEG_SLOPE * v.x;
            v.y = acc[j][3]; v.y = (v.y > 0.f) ? v.y : NEG_SLOPE * v.y;
            *reinterpret_cast<float2*>(C + (size_t)rB * DOUT + col) = v;
        }
    }
}

// ---------------------------------------------------------------------------
// CSR build: scalar histogram -> 2-level scan -> fused offsets+copy -> scatter
// ---------------------------------------------------------------------------
__global__ void hist_kernel(const int* __restrict__ rows, int* __restrict__ cnt, int E)
{
    int i = blockIdx.x * blockDim.x + threadIdx.x;
    if (i < E) atomicAdd(cnt + rows[i], 1);
}

#define SCAN_B 1024
__global__ __launch_bounds__(SCAN_B) void scan_blocks_kernel(
    const int* __restrict__ cnt, int* __restrict__ rowptr,
    int* __restrict__ bsums, int n)
{
    __shared__ int s[SCAN_B];
    const int tid = threadIdx.x;
    const int i = blockIdx.x * SCAN_B + tid;
    int v = (i < n) ? cnt[i] : 0;
    s[tid] = v;
    __syncthreads();
    #pragma unroll
    for (int off = 1; off < SCAN_B; off <<= 1) {
        int t = (tid >= off) ? s[tid - off] : 0;
        __syncthreads();
        s[tid] += t;
        __syncthreads();
    }
    if (i < n) rowptr[i] = s[tid] - v;
    if (tid == SCAN_B - 1) bsums[blockIdx.x] = s[tid];
}

__global__ __launch_bounds__(128) void scan_sums_kernel(int* __restrict__ bsums, int nb)
{
    __shared__ int s[128];
    const int tid = threadIdx.x;
    int v = (tid < nb) ? bsums[tid] : 0;
    s[tid] = v;
    __syncthreads();
    #pragma unroll
    for (int off = 1; off < 128; off <<= 1) {
        int t = (tid >= off) ? s[tid - off] : 0;
        __syncthreads();
        s[tid] += t;
        __syncthreads();
    }
    if (tid < nb) bsums[tid] = s[tid] - v;
}

// fused: finalize rowptr AND write the scatter-offset working copy
__global__ void add_offsets_copy_kernel(int* __restrict__ rowptr,
                                        int* __restrict__ tmpoff,
                                        const int* __restrict__ bsums, int n, int E)
{
    int i = blockIdx.x * blockDim.x + threadIdx.x;
    if (i < n) {
        int v = rowptr[i] + bsums[i >> 10];
        rowptr[i] = v;
        tmpoff[i] = v;
    }
    if (i == 0) rowptr[n] = E;
}

__global__ void scatter_kernel(const int* __restrict__ rows,
                               const int* __restrict__ cols,
                               const float* __restrict__ vals,
                               int* __restrict__ off,
                               float2* __restrict__ ecf, int E)
{
    int i = blockIdx.x * blockDim.x + threadIdx.x;
    if (i < E) {
        int r = rows[i];
        int p = atomicAdd(off + r, 1);
        ecf[p] = make_float2(__int_as_float(cols[i]), vals[i]);
    }
}

// ---------------------------------------------------------------------------
// CSR SpMM (R6-proven, unroll 2): 16 threads/row, float4/thread, no atomics.
// ---------------------------------------------------------------------------
__global__ __launch_bounds__(256) void spmm_csr_kernel(
    const int* __restrict__ rowptr, const float2* __restrict__ ecf,
    const float* __restrict__ x, float* __restrict__ out, int n)
{
    const int tid = threadIdx.x;
    const int row = blockIdx.x * 16 + (tid >> 4);
    const int c4 = (tid & 15) << 2;
    if (row >= n) return;

    const int s = __ldg(rowptr + row);
    const int e = __ldg(rowptr + row + 1);

    float4 a0 = make_float4(0.f, 0.f, 0.f, 0.f);
    float4 a1 = make_float4(0.f, 0.f, 0.f, 0.f);

    int i = s;
    for (; i + 2 <= e; i += 2) {
        const float2 cv0 = __ldg(ecf + i);
        const float2 cv1 = __ldg(ecf + i + 1);
        const int c0 = __float_as_int(cv0.x);
        const int c1 = __float_as_int(cv1.x);
        const float4 x0 = __ldg(reinterpret_cast<const float4*>(x + ((size_t)c0 << 6) + c4));
        const float4 x1 = __ldg(reinterpret_cast<const float4*>(x + ((size_t)c1 << 6) + c4));
        a0.x = fmaf(cv0.y, x0.x, a0.x); a0.y = fmaf(cv0.y, x0.y, a0.y);
        a0.z = fmaf(cv0.y, x0.z, a0.z); a0.w = fmaf(cv0.y, x0.w, a0.w);
        a1.x = fmaf(cv1.y, x1.x, a1.x); a1.y = fmaf(cv1.y, x1.y, a1.y);
        a1.z = fmaf(cv1.y, x1.z, a1.z); a1.w = fmaf(cv1.y, x1.w, a1.w);
    }
    if (i < e) {
        const float2 cv = __ldg(ecf + i);
        const int c0 = __float_as_int(cv.x);
        const float4 x0 = __ldg(reinterpret_cast<const float4*>(x + ((size_t)c0 << 6) + c4));
        a0.x = fmaf(cv.y, x0.x, a0.x); a0.y = fmaf(cv.y, x0.y, a0.y);
        a0.z = fmaf(cv.y, x0.z, a0.z); a0.w = fmaf(cv.y, x0.w, a0.w);
    }

    float4 r;
    r.x = a0.x + a1.x; r.y = a0.y + a1.y; r.z = a0.z + a1.z; r.w = a0.w + a1.w;
    *reinterpret_cast<float4*>(out + ((size_t)row << 6) + c4) = r;
}

// ---------------------------------------------------------------------------
// kernel_launch: fork the (GEMM-independent) CSR build onto a side stream so
// the captured graph overlaps it with the GEMM; join before SpMM-1.
// Stream/event handles are intentionally NOT destroyed (destroy during an
// active capture invalidates it; kernel_launch runs only a handful of times,
// and streams/events are not device-memory allocations).
// ---------------------------------------------------------------------------
extern "C" void kernel_launch(void* const* d_in, const int* in_sizes, int n_in,
                              void* d_out, int out_size)
{
    const float* features = (const float*)d_in[0];
    const float* weight   = (const float*)d_in[1];
    const int*   erows    = (const int*)d_in[2];
    const int*   ecols    = (const int*)d_in[3];
    const float* evals    = (const float*)d_in[4];
    float* out = (float*)d_out;

    const int n = in_sizes[0] / DIN;
    const int E = in_sizes[2];

    float* out_output = out;
    float* out_az     = out + (size_t)n * DOUT;

    float*    support = nullptr;
    unsigned* wp = nullptr;
    int *rowptr = nullptr, *tmpoff = nullptr, *bsums = nullptr;
    float2* ecf = nullptr;
    cudaGetSymbolAddress((void**)&support, g_support);
    cudaGetSymbolAddress((void**)&wp, g_Wp);
    cudaGetSymbolAddress((void**)&rowptr, g_rowptr);
    cudaGetSymbolAddress((void**)&tmpoff, g_tmpoff);
    cudaGetSymbolAddress((void**)&bsums, g_bsums);
    cudaGetSymbolAddress((void**)&ecf, g_ecf);

    cudaStream_t s2;
    cudaEvent_t  eFork, eJoin;
    cudaStreamCreateWithFlags(&s2, cudaStreamNonBlocking);
    cudaEventCreateWithFlags(&eFork, cudaEventDisableTiming);
    cudaEventCreateWithFlags(&eJoin, cudaEventDisableTiming);

    // ---- fork: side stream joins the capture graph ----
    cudaEventRecord(eFork, 0);
    cudaStreamWaitEvent(s2, eFork, 0);

    // ---- chain B (side stream): CSR build, independent of GEMM ----
    cudaMemsetAsync(tmpoff, 0, (size_t)n * sizeof(int), s2);
    hist_kernel<<<(E + 255) / 256, 256, 0, s2>>>(erows, tmpoff, E);
    const int nblocks = (n + SCAN_B - 1) / SCAN_B;
    scan_blocks_kernel<<<nblocks, SCAN_B, 0, s2>>>(tmpoff, rowptr, bsums, n);
    scan_sums_kernel<<<1, 128, 0, s2>>>(bsums, nblocks);
    add_offsets_copy_kernel<<<(n + 255) / 256, 256, 0, s2>>>(rowptr, tmpoff, bsums, n, E);
    scatter_kernel<<<(E + 255) / 256, 256, 0, s2>>>(erows, ecols, evals, tmpoff, ecf, E);
    cudaEventRecord(eJoin, s2);

    // ---- chain A (main stream): W pack + GEMM ----
    pack_w_kernel<<<((DIN / 2) * DOUT + 255) / 256, 256>>>(weight, wp);
    cudaFuncSetAttribute(gemm_bf16x3_kernel,
                         cudaFuncAttributeMaxDynamicSharedMemorySize, GEMM_SMEM_BYTES);
    gemm_bf16x3_kernel<<<(n + BM - 1) / BM, 256, GEMM_SMEM_BYTES>>>(features, wp, support, n);

    // ---- join: SpMMs need both support and the CSR ----
    cudaStreamWaitEvent(0, eJoin, 0);

    // ---- Phase 2: output = adj @ support ----
    spmm_csr_kernel<<<(n + 15) / 16, 256>>>(rowptr, ecf, support, out_output, n);

    // ---- Phase 3: az = adj @ output ----
    spmm_csr_kernel<<<(n + 15) / 16, 256>>>(rowptr, ecf, out_output, out_az, n);
}